// round 7
// baseline (speedup 1.0000x reference)
#include <cuda_runtime.h>
#include <cuda_bf16.h>
#include <cstddef>
#include <cstdint>

// Problem constants
#define N_TOK   32768        // B*T
#define DIM     128
#define KCODES  1024
#define NCB     8
#define M_TILE  64           // tokens per block
#define KC      128          // codes per chunk
#define TPB     256
#define GRID_MAIN (N_TOK / M_TILE)            // 512
#define NCHUNK  (NCB * KCODES / KC)           // 64

// Scratch (no allocations allowed -> device globals)
__device__ float g_wn[NCB * KCODES];
__device__ float g_part[GRID_MAIN];

// ---------------------------------------------------------------------------
__device__ __forceinline__ unsigned long long ffma2(unsigned long long a,
                                                    unsigned long long b,
                                                    unsigned long long c) {
    unsigned long long d;
    asm("fma.rn.f32x2 %0, %1, %2, %3;" : "=l"(d) : "l"(a), "l"(b), "l"(c));
    return d;
}
__device__ __forceinline__ void unpack2(unsigned long long v, float& lo, float& hi) {
    asm("mov.b64 {%0, %1}, %2;" : "=f"(lo), "=f"(hi) : "l"(v));
}
__device__ __forceinline__ void cp_async16(uint32_t dst_smem, const void* src) {
    asm volatile("cp.async.cg.shared.global [%0], [%1], 16;\n"
                 :: "r"(dst_smem), "l"(src));
}
#define CP_COMMIT() asm volatile("cp.async.commit_group;\n" ::: "memory")
#define CP_WAIT(n)  asm volatile("cp.async.wait_group %0;\n" :: "n"(n) : "memory")

// ---------------------------------------------------------------------------
// Shared memory (~105 KB -> 2 CTAs/SM)
//   res[m]       : 66 float2 rows (528B = 33x16B, 16B-aligned float4 loads;
//                  a-operands are full-warp broadcasts)
//   code_p[p][k] : d2-pair-major chunk; float4 = dims 4p..4p+3 of code k.
//                  b-loads are lane-contiguous LDS.128 (conflict-free).
// ---------------------------------------------------------------------------
struct SB {
    float2 res[M_TILE][66];            // 33,792 B
    float4 code_p[DIM / 4][KC + 1];    // 32 x 129 x 16 = 66,048 B
    float  wn[KCODES];                 //  4,096 B
    int    codes_all[NCB][M_TILE];     //  2,048 B
    float  red[TPB];                   //  1,024 B
};

extern __shared__ char smraw[];

// ---------------------------------------------------------------------------
// Kernel 1: ||w||^2 per code (warp per code; lane-strided + xor tree)
// ---------------------------------------------------------------------------
__global__ void wnorm_kernel(const float* __restrict__ cb) {
    int gwarp = (blockIdx.x * blockDim.x + threadIdx.x) >> 5;
    int lane  = threadIdx.x & 31;
    if (gwarp >= NCB * KCODES) return;
    const float* w = cb + (size_t)gwarp * DIM;
    float s = 0.f;
    #pragma unroll
    for (int i = 0; i < DIM / 32; ++i) {
        float v = w[lane + 32 * i];
        s = __fmaf_rn(v, v, s);
    }
    #pragma unroll
    for (int o = 16; o > 0; o >>= 1)
        s = __fadd_rn(s, __shfl_xor_sync(0xFFFFFFFFu, s, o));
    if (lane == 0) g_wn[gwarp] = s;
}

// ---------------------------------------------------------------------------
// stage one chunk: gmem float4 e = k*32 + p  ->  code_p[p][k]  (coalesced LDG)
// ---------------------------------------------------------------------------
__device__ __forceinline__ void stage_chunk(SB* sm, const float4* cb4,
                                            int t, int tid) {
    const float4* src = cb4 + (size_t)t * (KC * DIM / 4);
    #pragma unroll
    for (int r = 0; r < (KC * DIM / 4) / TPB; ++r) {   // 16 per thread
        int e = tid + r * TPB;
        int k = e >> 5, p = e & 31;
        uint32_t dst = (uint32_t)__cvta_generic_to_shared(&sm->code_p[p][k]);
        cp_async16(dst, src + e);
    }
    CP_COMMIT();
}

// ---------------------------------------------------------------------------
// Kernel 2: main residual-VQ. 2 CTAs/SM; warp owns 8 tokens end-to-end,
// lane owns 4 codes per 128-code chunk. Scoring chain byte-identical to the
// validated kernel: acc = ffma2 over d2 ascending (x then y per float4 pair);
//   u = fadd( fma(-2, fadd(lo,hi), rr), wn ); argmin, first-index ties.
// ---------------------------------------------------------------------------
__global__ __launch_bounds__(TPB, 2) void rvq_main(
    const float* __restrict__ emb, const float* __restrict__ cb,
    float* __restrict__ out_codes, float* __restrict__ out_quant)
{
    SB* sm = reinterpret_cast<SB*>(smraw);
    const int tid  = threadIdx.x;
    const int wid  = tid >> 5;          // 8 warps; warp owns tokens wid*8..+7
    const int lane = tid & 31;
    const int n0   = blockIdx.x * M_TILE;
    const float4* cb4 = reinterpret_cast<const float4*>(cb);

    // residual <- embeddings (warp-private rows) + rr (validated chain)
    float rrv[8];
    #pragma unroll
    for (int i = 0; i < 8; ++i) {
        int m = wid * 8 + i;
        const float* er = emb + (size_t)(n0 + m) * DIM;
        float* rowf = reinterpret_cast<float*>(&sm->res[m][0]);
        float s = 0.f;
        #pragma unroll
        for (int q = 0; q < DIM / 32; ++q) {
            int d = lane + 32 * q;
            float v = er[d];
            rowf[d] = v;
            s = __fmaf_rn(v, v, s);
        }
        #pragma unroll
        for (int o = 16; o > 0; o >>= 1)
            s = __fadd_rn(s, __shfl_xor_sync(0xFFFFFFFFu, s, o));
        rrv[i] = s;
    }

    float lsum = 0.f;

    for (int c = 0; c < NCB; ++c) {
        const float* cbc = cb + (size_t)c * KCODES * DIM;

        __syncthreads();   // prev cb epilogue done -> wn safe to overwrite
        for (int e = tid; e < KCODES; e += TPB)
            sm->wn[e] = g_wn[c * KCODES + e];

        float bU[8]; int bI[8];
        #pragma unroll
        for (int i = 0; i < 8; ++i) { bU[i] = 1e30f; bI[i] = 0; }

        for (int tch = c * 8; tch < c * 8 + 8; ++tch) {
            const int kb = (tch & 7) * KC;

            __syncthreads();              // all readers of code_p done
            stage_chunk(sm, cb4, tch, tid);
            CP_WAIT(0);
            __syncthreads();              // chunk visible (+ wn on first)

            unsigned long long acc[8][4];
            #pragma unroll
            for (int i = 0; i < 8; ++i)
                #pragma unroll
                for (int j = 0; j < 4; ++j) acc[i][j] = 0ull;

            const ulonglong2* arow[8];
            #pragma unroll
            for (int i = 0; i < 8; ++i)
                arow[i] = reinterpret_cast<const ulonglong2*>(&sm->res[wid * 8 + i][0]);

            #pragma unroll 4
            for (int p = 0; p < DIM / 4; ++p) {
                ulonglong2 b[4];
                #pragma unroll
                for (int j = 0; j < 4; ++j)
                    b[j] = *reinterpret_cast<const ulonglong2*>(
                               &sm->code_p[p][lane + 32 * j]);
                #pragma unroll
                for (int i = 0; i < 8; ++i) {
                    ulonglong2 a = arow[i][p];   // warp broadcast LDS.128
                    #pragma unroll
                    for (int j = 0; j < 4; ++j)
                        acc[i][j] = ffma2(a.y, b[j].y,
                                          ffma2(a.x, b[j].x, acc[i][j]));
                }
            }

            // u = fl(fl(rr - 2m) + ww); running argmin, k ascending per lane
            #pragma unroll
            for (int j = 0; j < 4; ++j) {
                int   kl = lane + 32 * j;
                float wn = sm->wn[kb + kl];
                int   k  = kb + kl;
                #pragma unroll
                for (int i = 0; i < 8; ++i) {
                    float lo, hi; unpack2(acc[i][j], lo, hi);
                    float m_ = __fadd_rn(lo, hi);
                    float t_ = __fmaf_rn(-2.0f, m_, rrv[i]);
                    float u  = __fadd_rn(t_, wn);
                    if (u < bU[i]) { bU[i] = u; bI[i] = k; }
                }
            }
        }

        // warp argmin over 32 lanes; (minU, minK-on-tie) xor tree lands the
        // result in all lanes == global first-index argmin
        #pragma unroll
        for (int i = 0; i < 8; ++i) {
            float u = bU[i]; int k = bI[i];
            #pragma unroll
            for (int o = 1; o < 32; o <<= 1) {
                float ou = __shfl_xor_sync(0xFFFFFFFFu, u, o);
                int   ok = __shfl_xor_sync(0xFFFFFFFFu, k, o);
                if (ou < u || (ou == u && ok < k)) { u = ou; k = ok; }
            }
            bI[i] = k;
            if (lane == 0) {
                int m = wid * 8 + i;
                sm->codes_all[c][m] = k;
                out_codes[(size_t)(n0 + m) * NCB + c] = (float)k;
            }
        }

        // fused residual update + rr for next step (exact reference chains)
        #pragma unroll
        for (int i = 0; i < 8; ++i) {
            int m = wid * 8 + i;
            const float* wrow = cbc + (size_t)bI[i] * DIM;
            float* rowf = reinterpret_cast<float*>(&sm->res[m][0]);
            float s = 0.f;
            #pragma unroll
            for (int q = 0; q < DIM / 32; ++q) {
                int d = lane + 32 * q;
                float w = wrow[d];
                float r = __fadd_rn(rowf[d], -w);
                rowf[d] = r;
                s = __fmaf_rn(r, r, s);      // rr chain (q ascending)
                lsum += r * r;               // loss (order-insensitive tol)
            }
            #pragma unroll
            for (int o = 16; o > 0; o >>= 1)
                s = __fadd_rn(s, __shfl_xor_sync(0xFFFFFFFFu, s, o));
            rrv[i] = s;
        }
    }

    // quantized output: q = sum_c w[idx_c] (reference add chain from 0),
    // straight-through: out = e + (q - e)
    __syncthreads();   // codes_all from all warps
    for (int e = tid; e < M_TILE * DIM; e += TPB) {
        int m = e >> 7, d = e & (DIM - 1);
        float q = cb[(size_t)sm->codes_all[0][m] * DIM + d];
        #pragma unroll
        for (int c = 1; c < NCB; ++c)
            q = __fadd_rn(q, cb[(size_t)c * KCODES * DIM
                               + (size_t)sm->codes_all[c][m] * DIM + d]);
        size_t g = (size_t)(n0 + m) * DIM + d;
        float e0 = emb[g];
        out_quant[g] = __fadd_rn(e0, __fadd_rn(q, -e0));
    }

    // deterministic block loss reduction
    sm->red[tid] = lsum;
    __syncthreads();
    for (int s = TPB / 2; s > 0; s >>= 1) {
        if (tid < s) sm->red[tid] += sm->red[tid + s];
        __syncthreads();
    }
    if (tid == 0) g_part[blockIdx.x] = sm->red[0];
}

// ---------------------------------------------------------------------------
__global__ void loss_final(float* __restrict__ out_loss) {
    __shared__ float red[GRID_MAIN];
    int t = threadIdx.x;
    red[t] = g_part[t];
    __syncthreads();
    for (int s = GRID_MAIN / 2; s > 0; s >>= 1) {
        if (t < s) red[t] += red[t + s];
        __syncthreads();
    }
    if (t == 0)
        out_loss[0] = red[0] * (1.0f / ((float)N_TOK * (float)DIM * (float)NCB));
}

// ---------------------------------------------------------------------------
extern "C" void kernel_launch(void* const* d_in, const int* in_sizes, int n_in,
                              void* d_out, int out_size) {
    const float* emb = (const float*)d_in[0];   // [8,4096,128] f32
    const float* cb  = (const float*)d_in[1];   // [8,1024,128] f32

    float* out_codes = (float*)d_out;                         // 32768*8
    float* out_quant = out_codes + (size_t)N_TOK * NCB;       // 32768*128
    float* out_loss  = out_quant + (size_t)N_TOK * DIM;       // 1

    cudaFuncSetAttribute(rvq_main, cudaFuncAttributeMaxDynamicSharedMemorySize,
                         (int)sizeof(SB));

    wnorm_kernel<<<(NCB * KCODES) / 8, 256>>>(cb);
    rvq_main<<<GRID_MAIN, TPB, sizeof(SB)>>>(emb, cb, out_codes, out_quant);
    loss_final<<<1, GRID_MAIN>>>(out_loss);
}

// round 8
// speedup vs baseline: 1.0005x; 1.0005x over previous
#include <cuda_runtime.h>
#include <cuda_bf16.h>
#include <cstddef>
#include <cstdint>

// Problem constants
#define N_TOK   32768        // B*T
#define DIM     128
#define KCODES  1024
#define NCB     8
#define M_TILE  64           // tokens per block
#define KC      128          // codes per chunk
#define TPB     256
#define GRID_MAIN (N_TOK / M_TILE)            // 512
#define NCHUNK  (NCB * KCODES / KC)           // 64

// Scratch (no allocations allowed -> device globals)
__device__ float g_wn[NCB * KCODES];
__device__ float g_part[GRID_MAIN];

// ---------------------------------------------------------------------------
__device__ __forceinline__ unsigned long long ffma2(unsigned long long a,
                                                    unsigned long long b,
                                                    unsigned long long c) {
    unsigned long long d;
    asm("fma.rn.f32x2 %0, %1, %2, %3;" : "=l"(d) : "l"(a), "l"(b), "l"(c));
    return d;
}
__device__ __forceinline__ void unpack2(unsigned long long v, float& lo, float& hi) {
    asm("mov.b64 {%0, %1}, %2;" : "=f"(lo), "=f"(hi) : "l"(v));
}
__device__ __forceinline__ void cp_async16(uint32_t dst_smem, const void* src) {
    asm volatile("cp.async.cg.shared.global [%0], [%1], 16;\n"
                 :: "r"(dst_smem), "l"(src));
}
#define CP_COMMIT() asm volatile("cp.async.commit_group;\n" ::: "memory")
#define CP_WAIT(n)  asm volatile("cp.async.wait_group %0;\n" :: "n"(n) : "memory")

// ---------------------------------------------------------------------------
// Shared memory (~105 KB -> 2 CTAs/SM)
//   res[m]       : 66 float2 rows (528B = 33x16B, 16B-aligned float4 loads;
//                  a-operands are full-warp broadcasts)
//   code_p[p][k] : d2-pair-major chunk; float4 = dims 4p..4p+3 of code k.
//                  b-loads are lane-contiguous LDS.128 (conflict-free).
// ---------------------------------------------------------------------------
struct SB {
    float2 res[M_TILE][66];            // 33,792 B
    float4 code_p[DIM / 4][KC + 1];    // 32 x 129 x 16 = 66,048 B
    float  wn[KCODES];                 //  4,096 B
    int    codes_all[NCB][M_TILE];     //  2,048 B
    float  red[TPB];                   //  1,024 B
};

extern __shared__ char smraw[];

// ---------------------------------------------------------------------------
// Kernel 1: ||w||^2 per code (warp per code; lane-strided + xor tree)
// ---------------------------------------------------------------------------
__global__ void wnorm_kernel(const float* __restrict__ cb) {
    int gwarp = (blockIdx.x * blockDim.x + threadIdx.x) >> 5;
    int lane  = threadIdx.x & 31;
    if (gwarp >= NCB * KCODES) return;
    const float* w = cb + (size_t)gwarp * DIM;
    float s = 0.f;
    #pragma unroll
    for (int i = 0; i < DIM / 32; ++i) {
        float v = w[lane + 32 * i];
        s = __fmaf_rn(v, v, s);
    }
    #pragma unroll
    for (int o = 16; o > 0; o >>= 1)
        s = __fadd_rn(s, __shfl_xor_sync(0xFFFFFFFFu, s, o));
    if (lane == 0) g_wn[gwarp] = s;
}

// ---------------------------------------------------------------------------
// stage one chunk: gmem float4 e = k*32 + p  ->  code_p[p][k]  (coalesced LDG)
// ---------------------------------------------------------------------------
__device__ __forceinline__ void stage_chunk(SB* sm, const float4* cb4,
                                            int t, int tid) {
    const float4* src = cb4 + (size_t)t * (KC * DIM / 4);
    #pragma unroll
    for (int r = 0; r < (KC * DIM / 4) / TPB; ++r) {   // 16 per thread
        int e = tid + r * TPB;
        int k = e >> 5, p = e & 31;
        uint32_t dst = (uint32_t)__cvta_generic_to_shared(&sm->code_p[p][k]);
        cp_async16(dst, src + e);
    }
    CP_COMMIT();
}

// ---------------------------------------------------------------------------
// Kernel 2: main residual-VQ. 2 CTAs/SM; warp owns 8 tokens end-to-end,
// lane owns 4 codes per 128-code chunk. Scoring chain byte-identical to the
// validated kernel: acc = ffma2 over d2 ascending (x then y per float4 pair);
//   u = fadd( fma(-2, fadd(lo,hi), rr), wn ); argmin, first-index ties.
// ---------------------------------------------------------------------------
__global__ __launch_bounds__(TPB, 2) void rvq_main(
    const float* __restrict__ emb, const float* __restrict__ cb,
    float* __restrict__ out_codes, float* __restrict__ out_quant)
{
    SB* sm = reinterpret_cast<SB*>(smraw);
    const int tid  = threadIdx.x;
    const int wid  = tid >> 5;          // 8 warps; warp owns tokens wid*8..+7
    const int lane = tid & 31;
    const int n0   = blockIdx.x * M_TILE;
    const float4* cb4 = reinterpret_cast<const float4*>(cb);

    // residual <- embeddings (warp-private rows) + rr (validated chain)
    float rrv[8];
    #pragma unroll
    for (int i = 0; i < 8; ++i) {
        int m = wid * 8 + i;
        const float* er = emb + (size_t)(n0 + m) * DIM;
        float* rowf = reinterpret_cast<float*>(&sm->res[m][0]);
        float s = 0.f;
        #pragma unroll
        for (int q = 0; q < DIM / 32; ++q) {
            int d = lane + 32 * q;
            float v = er[d];
            rowf[d] = v;
            s = __fmaf_rn(v, v, s);
        }
        #pragma unroll
        for (int o = 16; o > 0; o >>= 1)
            s = __fadd_rn(s, __shfl_xor_sync(0xFFFFFFFFu, s, o));
        rrv[i] = s;
    }

    float lsum = 0.f;

    for (int c = 0; c < NCB; ++c) {
        const float* cbc = cb + (size_t)c * KCODES * DIM;

        __syncthreads();   // prev cb epilogue done -> wn safe to overwrite
        for (int e = tid; e < KCODES; e += TPB)
            sm->wn[e] = g_wn[c * KCODES + e];

        float bU[8]; int bI[8];
        #pragma unroll
        for (int i = 0; i < 8; ++i) { bU[i] = 1e30f; bI[i] = 0; }

        for (int tch = c * 8; tch < c * 8 + 8; ++tch) {
            const int kb = (tch & 7) * KC;

            __syncthreads();              // all readers of code_p done
            stage_chunk(sm, cb4, tch, tid);
            CP_WAIT(0);
            __syncthreads();              // chunk visible (+ wn on first)

            unsigned long long acc[8][4];
            #pragma unroll
            for (int i = 0; i < 8; ++i)
                #pragma unroll
                for (int j = 0; j < 4; ++j) acc[i][j] = 0ull;

            const ulonglong2* arow[8];
            #pragma unroll
            for (int i = 0; i < 8; ++i)
                arow[i] = reinterpret_cast<const ulonglong2*>(&sm->res[wid * 8 + i][0]);

            #pragma unroll 4
            for (int p = 0; p < DIM / 4; ++p) {
                ulonglong2 b[4];
                #pragma unroll
                for (int j = 0; j < 4; ++j)
                    b[j] = *reinterpret_cast<const ulonglong2*>(
                               &sm->code_p[p][lane + 32 * j]);
                #pragma unroll
                for (int i = 0; i < 8; ++i) {
                    ulonglong2 a = arow[i][p];   // warp broadcast LDS.128
                    #pragma unroll
                    for (int j = 0; j < 4; ++j)
                        acc[i][j] = ffma2(a.y, b[j].y,
                                          ffma2(a.x, b[j].x, acc[i][j]));
                }
            }

            // u = fl(fl(rr - 2m) + ww); running argmin, k ascending per lane
            #pragma unroll
            for (int j = 0; j < 4; ++j) {
                int   kl = lane + 32 * j;
                float wn = sm->wn[kb + kl];
                int   k  = kb + kl;
                #pragma unroll
                for (int i = 0; i < 8; ++i) {
                    float lo, hi; unpack2(acc[i][j], lo, hi);
                    float m_ = __fadd_rn(lo, hi);
                    float t_ = __fmaf_rn(-2.0f, m_, rrv[i]);
                    float u  = __fadd_rn(t_, wn);
                    if (u < bU[i]) { bU[i] = u; bI[i] = k; }
                }
            }
        }

        // warp argmin over 32 lanes; (minU, minK-on-tie) xor tree lands the
        // result in all lanes == global first-index argmin
        #pragma unroll
        for (int i = 0; i < 8; ++i) {
            float u = bU[i]; int k = bI[i];
            #pragma unroll
            for (int o = 1; o < 32; o <<= 1) {
                float ou = __shfl_xor_sync(0xFFFFFFFFu, u, o);
                int   ok = __shfl_xor_sync(0xFFFFFFFFu, k, o);
                if (ou < u || (ou == u && ok < k)) { u = ou; k = ok; }
            }
            bI[i] = k;
            if (lane == 0) {
                int m = wid * 8 + i;
                sm->codes_all[c][m] = k;
                out_codes[(size_t)(n0 + m) * NCB + c] = (float)k;
            }
        }

        // fused residual update + rr for next step (exact reference chains)
        #pragma unroll
        for (int i = 0; i < 8; ++i) {
            int m = wid * 8 + i;
            const float* wrow = cbc + (size_t)bI[i] * DIM;
            float* rowf = reinterpret_cast<float*>(&sm->res[m][0]);
            float s = 0.f;
            #pragma unroll
            for (int q = 0; q < DIM / 32; ++q) {
                int d = lane + 32 * q;
                float w = wrow[d];
                float r = __fadd_rn(rowf[d], -w);
                rowf[d] = r;
                s = __fmaf_rn(r, r, s);      // rr chain (q ascending)
                lsum += r * r;               // loss (order-insensitive tol)
            }
            #pragma unroll
            for (int o = 16; o > 0; o >>= 1)
                s = __fadd_rn(s, __shfl_xor_sync(0xFFFFFFFFu, s, o));
            rrv[i] = s;
        }
    }

    // quantized output: q = sum_c w[idx_c] (reference add chain from 0),
    // straight-through: out = e + (q - e)
    __syncthreads();   // codes_all from all warps
    for (int e = tid; e < M_TILE * DIM; e += TPB) {
        int m = e >> 7, d = e & (DIM - 1);
        float q = cb[(size_t)sm->codes_all[0][m] * DIM + d];
        #pragma unroll
        for (int c = 1; c < NCB; ++c)
            q = __fadd_rn(q, cb[(size_t)c * KCODES * DIM
                               + (size_t)sm->codes_all[c][m] * DIM + d]);
        size_t g = (size_t)(n0 + m) * DIM + d;
        float e0 = emb[g];
        out_quant[g] = __fadd_rn(e0, __fadd_rn(q, -e0));
    }

    // deterministic block loss reduction
    sm->red[tid] = lsum;
    __syncthreads();
    for (int s = TPB / 2; s > 0; s >>= 1) {
        if (tid < s) sm->red[tid] += sm->red[tid + s];
        __syncthreads();
    }
    if (tid == 0) g_part[blockIdx.x] = sm->red[0];
}

// ---------------------------------------------------------------------------
__global__ void loss_final(float* __restrict__ out_loss) {
    __shared__ float red[GRID_MAIN];
    int t = threadIdx.x;
    red[t] = g_part[t];
    __syncthreads();
    for (int s = GRID_MAIN / 2; s > 0; s >>= 1) {
        if (t < s) red[t] += red[t + s];
        __syncthreads();
    }
    if (t == 0)
        out_loss[0] = red[0] * (1.0f / ((float)N_TOK * (float)DIM * (float)NCB));
}

// ---------------------------------------------------------------------------
extern "C" void kernel_launch(void* const* d_in, const int* in_sizes, int n_in,
                              void* d_out, int out_size) {
    const float* emb = (const float*)d_in[0];   // [8,4096,128] f32
    const float* cb  = (const float*)d_in[1];   // [8,1024,128] f32

    float* out_codes = (float*)d_out;                         // 32768*8
    float* out_quant = out_codes + (size_t)N_TOK * NCB;       // 32768*128
    float* out_loss  = out_quant + (size_t)N_TOK * DIM;       // 1

    cudaFuncSetAttribute(rvq_main, cudaFuncAttributeMaxDynamicSharedMemorySize,
                         (int)sizeof(SB));

    wnorm_kernel<<<(NCB * KCODES) / 8, 256>>>(cb);
    rvq_main<<<GRID_MAIN, TPB, sizeof(SB)>>>(emb, cb, out_codes, out_quant);
    loss_final<<<1, GRID_MAIN>>>(out_loss);
}